// round 15
// baseline (speedup 1.0000x reference)
#include <cuda_runtime.h>
#include <cuda_fp16.h>
#include <cstdint>

// Problem constants
constexpr int Bc = 2;
constexpr int Sc = 2048;
constexpr int Dc = 1024;
constexpr int Hc = 16;
constexpr int DKc = 64;
constexpr int Mc = Bc * Sc;  // 4096

// Half scratch (device globals: allocation-free)
__device__ __half g_q16[(size_t)Mc * Dc];
__device__ __half g_k16[(size_t)Mc * Dc];
__device__ __half g_v16[(size_t)Mc * Dc];
__device__ __half g_Wq16[(size_t)Dc * Dc];
__device__ __half g_Wk16[(size_t)Dc * Dc];
__device__ __half g_Wv16[(size_t)Dc * Dc];
__device__ __half g_Wo16[(size_t)Dc * Dc];
__device__ __half g_Qh[(size_t)Bc * Hc * Sc * DKc];   // [b,h,s,dk]
__device__ __half g_Kh[(size_t)Bc * Hc * Sc * DKc];   // [b,h,s,dk]
__device__ __half g_Vt[(size_t)Bc * Hc * DKc * Sc];   // [b,h,dk,s] (transposed)
__device__ __half g_att[(size_t)Mc * Dc];             // [b,s,d]

// ---------------------------------------------------------------------------
// Helpers
// ---------------------------------------------------------------------------
__device__ __forceinline__ uint32_t smem_u32(const void* p) {
    uint32_t a;
    asm("{ .reg .u64 t; cvta.to.shared.u64 t, %1; cvt.u32.u64 %0, t; }"
        : "=r"(a) : "l"(p));
    return a;
}
__device__ __forceinline__ void cp_async16(uint32_t s, const void* g) {
    asm volatile("cp.async.cg.shared.global [%0], [%1], 16;" :: "r"(s), "l"(g));
}
__device__ __forceinline__ void cp_commit() {
    asm volatile("cp.async.commit_group;" ::: "memory");
}
template <int N>
__device__ __forceinline__ void cp_wait() {
    asm volatile("cp.async.wait_group %0;" :: "n"(N) : "memory");
}
__device__ __forceinline__ uint32_t pack_h2(float a, float b) {
    __half2 h = __floats2half2_rn(a, b);
    return *reinterpret_cast<uint32_t*>(&h);
}
__device__ __forceinline__ void mma_f16(float* C, const uint32_t* A,
                                        const uint32_t* B) {
    asm volatile(
        "mma.sync.aligned.m16n8k16.row.col.f32.f16.f16.f32 "
        "{%0,%1,%2,%3}, {%4,%5,%6,%7}, {%8,%9}, {%0,%1,%2,%3};"
        : "+f"(C[0]), "+f"(C[1]), "+f"(C[2]), "+f"(C[3])
        : "r"(A[0]), "r"(A[1]), "r"(A[2]), "r"(A[3]), "r"(B[0]), "r"(B[1]));
}
__device__ __forceinline__ void ldm_x4(uint32_t& r0, uint32_t& r1, uint32_t& r2,
                                       uint32_t& r3, uint32_t addr) {
    asm volatile("ldmatrix.sync.aligned.m8n8.x4.shared.b16 {%0,%1,%2,%3}, [%4];"
                 : "=r"(r0), "=r"(r1), "=r"(r2), "=r"(r3) : "r"(addr));
}

// ---------------------------------------------------------------------------
// Prepass: fp32 -> fp16 conversion of inputs + weights.
// ---------------------------------------------------------------------------
__global__ void __launch_bounds__(256) cvt_kernel(const float* __restrict__ q,
                                                  const float* __restrict__ k,
                                                  const float* __restrict__ v,
                                                  const float* __restrict__ Wq,
                                                  const float* __restrict__ Wk,
                                                  const float* __restrict__ Wv,
                                                  const float* __restrict__ Wo) {
    constexpr size_t NIN = 1048576;   // float4 per input
    constexpr size_t NW = 262144;     // float4 per weight
    const size_t total = 3 * NIN + 4 * NW;
    for (size_t idx = blockIdx.x * 256 + threadIdx.x; idx < total;
         idx += (size_t)gridDim.x * 256) {
        const float* src;
        __half* dst;
        size_t off;
        if (idx < 3 * NIN) {
            const int w = (int)(idx / NIN);
            off = idx % NIN;
            src = (w == 0) ? q : (w == 1) ? k : v;
            dst = (w == 0) ? g_q16 : (w == 1) ? g_k16 : g_v16;
        } else {
            const size_t r = idx - 3 * NIN;
            const int w = (int)(r / NW);
            off = r % NW;
            src = (w == 0) ? Wq : (w == 1) ? Wk : (w == 2) ? Wv : Wo;
            dst = (w == 0) ? g_Wq16 : (w == 1) ? g_Wk16 : (w == 2) ? g_Wv16 : g_Wo16;
        }
        float4 f = reinterpret_cast<const float4*>(src)[off];
        uint2 u;
        u.x = pack_h2(f.x, f.y);
        u.y = pack_h2(f.z, f.w);
        reinterpret_cast<uint2*>(dst)[off] = u;
    }
}

// ---------------------------------------------------------------------------
// fp16 projection GEMM, ldmatrix + software-pipelined fragments.
// CTA 128x128, BK=64 halfs, double-buffered cp.async, 8 warps (4m x 2n).
// ---------------------------------------------------------------------------
constexpr int PBKH = 64;
constexpr int PSTRH = 72;
constexpr int PTILEH = 128 * PSTRH;
constexpr int PROJ_SMEM = 4 * PTILEH * 2;  // 73728 B

template <int MODE>
__device__ __forceinline__ void proj_body(const __half* __restrict__ A,
                                          const __half* __restrict__ W,
                                          const float* __restrict__ bias,
                                          void* __restrict__ outp,
                                          __half* sm, int row0, int col0) {
    const uint32_t smb = smem_u32(sm);
    const int tid = threadIdx.x;
    const int wid = tid >> 5;
    const int lid = tid & 31;
    const int g = lid >> 2;
    const int t4 = lid & 3;
    const int wm = wid & 3;
    const int wn = wid >> 2;
    const int qq = lid >> 3;
    const int rr = lid & 7;

    const uint32_t aoff =
        (uint32_t)((wm * 32 + (qq & 1) * 8 + rr) * PSTRH + (qq >> 1) * 8) * 2;
    const uint32_t boff =
        (uint32_t)((wn * 64 + (qq >> 1) * 8 + rr) * PSTRH + (qq & 1) * 8) * 2;

    const __half* Ap = A + (size_t)row0 * Dc;
    const __half* Wp = W + (size_t)col0 * Dc;

    auto load_tiles = [&](int kb, int buf) {
        const int k0 = kb * PBKH;
        const uint32_t abase = smb + (uint32_t)(buf * 2 * PTILEH) * 2;
        const uint32_t bbase = abase + (uint32_t)PTILEH * 2;
#pragma unroll
        for (int i = 0; i < 4; i++) {
            const int ch = tid + i * 256;
            const int r = ch >> 3;
            const int c = ch & 7;
            const uint32_t so = (uint32_t)(r * PSTRH + c * 8) * 2;
            cp_async16(abase + so, Ap + (size_t)r * Dc + k0 + c * 8);
            cp_async16(bbase + so, Wp + (size_t)r * Dc + k0 + c * 8);
        }
        cp_commit();
    };

    float acc[2][8][4] = {};

    load_tiles(0, 0);
    const int NKB = Dc / PBKH;  // 16
    for (int kb = 0; kb < NKB; kb++) {
        const int buf = kb & 1;
        if (kb + 1 < NKB) {
            load_tiles(kb + 1, buf ^ 1);
            cp_wait<1>();
        } else {
            cp_wait<0>();
        }
        __syncthreads();

        const uint32_t abase = smb + (uint32_t)(buf * 2 * PTILEH) * 2;
        const uint32_t bbase = abase + (uint32_t)PTILEH * 2;

        // software-pipelined fragment loads over 4 ks steps
        uint32_t af[2][2][4], bf[2][8][2];
        ldm_x4(af[0][0][0], af[0][0][1], af[0][0][2], af[0][0][3], abase + aoff);
        ldm_x4(af[0][1][0], af[0][1][1], af[0][1][2], af[0][1][3],
               abase + aoff + 16 * PSTRH * 2);
#pragma unroll
        for (int p = 0; p < 4; p++) {
            ldm_x4(bf[0][2 * p][0], bf[0][2 * p][1], bf[0][2 * p + 1][0],
                   bf[0][2 * p + 1][1],
                   bbase + boff + (uint32_t)(p * 16 * PSTRH) * 2);
        }
#pragma unroll
        for (int ks = 0; ks < 4; ks++) {
            const int cur = ks & 1;
            const int nxt = cur ^ 1;
            if (ks < 3) {
                ldm_x4(af[nxt][0][0], af[nxt][0][1], af[nxt][0][2], af[nxt][0][3],
                       abase + aoff + (ks + 1) * 32);
                ldm_x4(af[nxt][1][0], af[nxt][1][1], af[nxt][1][2], af[nxt][1][3],
                       abase + aoff + 16 * PSTRH * 2 + (ks + 1) * 32);
#pragma unroll
                for (int p = 0; p < 4; p++) {
                    ldm_x4(bf[nxt][2 * p][0], bf[nxt][2 * p][1],
                           bf[nxt][2 * p + 1][0], bf[nxt][2 * p + 1][1],
                           bbase + boff + (uint32_t)(p * 16 * PSTRH) * 2 +
                               (ks + 1) * 32);
                }
            }
#pragma unroll
            for (int nt = 0; nt < 8; nt++)
#pragma unroll
                for (int mt = 0; mt < 2; mt++)
                    mma_f16(acc[mt][nt], af[cur][mt], bf[cur][nt]);
        }
        __syncthreads();
    }

    // Epilogue
#pragma unroll
    for (int mt = 0; mt < 2; mt++) {
#pragma unroll
        for (int half_ = 0; half_ < 2; half_++) {
            const int m = row0 + wm * 32 + mt * 16 + g + half_ * 8;
            const int b = m >> 11;
            const int s = m & 2047;
#pragma unroll
            for (int nt = 0; nt < 8; nt++) {
                const int n = col0 + wn * 64 + nt * 8 + t4 * 2;
                const float ox = acc[mt][nt][half_ * 2 + 0] + bias[n];
                const float oy = acc[mt][nt][half_ * 2 + 1] + bias[n + 1];
                if (MODE == 0) {
                    float2 o = {ox, oy};
                    *reinterpret_cast<float2*>((float*)outp + (size_t)m * Dc + n) = o;
                } else if (MODE == 1) {
                    const int h = n >> 6, dk = n & 63;
                    __half2 o = __floats2half2_rn(ox, oy);
                    *reinterpret_cast<__half2*>(
                        (__half*)outp + ((size_t)((b * Hc + h) * Sc + s) << 6) + dk) = o;
                } else {
                    const int h = n >> 6, dk = n & 63;
                    __half* dst = (__half*)outp +
                                  ((size_t)((b * Hc + h) * DKc + dk)) * Sc + s;
                    dst[0] = __float2half_rn(ox);
                    dst[Sc] = __float2half_rn(oy);
                }
            }
        }
    }
}

__global__ void __launch_bounds__(256) proj_qkv_kernel(
    const float* __restrict__ bq, const float* __restrict__ bk,
    const float* __restrict__ bv) {
    extern __shared__ __half smh[];
    const int z = blockIdx.z;
    const int row0 = blockIdx.y * 128, col0 = blockIdx.x * 128;
    if (z == 0) {
        proj_body<1>(g_q16, g_Wq16, bq, g_Qh, smh, row0, col0);
    } else if (z == 1) {
        proj_body<1>(g_k16, g_Wk16, bk, g_Kh, smh, row0, col0);
    } else {
        proj_body<2>(g_v16, g_Wv16, bv, g_Vt, smh, row0, col0);
    }
}

__global__ void __launch_bounds__(256) proj_o_kernel(const float* __restrict__ bo,
                                                     float* __restrict__ out) {
    extern __shared__ __half smh[];
    proj_body<0>(g_att, g_Wo16, bo, out, smh, blockIdx.y * 128, blockIdx.x * 128);
}

// ---------------------------------------------------------------------------
// Flash attention (causal), fp16 mma + ldmatrix, pipelined fragments,
// double-buffered K/V, reversed-qt schedule. 8 warps x 16 rows.
// ---------------------------------------------------------------------------
constexpr int AT = 72;            // half stride (36 words)
constexpr int KV_TILE = 64 * AT;  // halfs
constexpr int ATTN_SMEM_HALFS = 2 * KV_TILE + 2 * KV_TILE + 128 * AT;
constexpr int ATTN_SMEM_BYTES = ATTN_SMEM_HALFS * 2;  // 55296

__global__ void __launch_bounds__(256, 2) attn_kernel(float* /*unused*/) {
    extern __shared__ __half smh[];

    const int tid = threadIdx.x;
    const int wid = tid >> 5;
    const int lid = tid & 31;
    const int g = lid >> 2;
    const int t4 = lid & 3;
    const int qq = lid >> 3;
    const int rr = lid & 7;
    const int qt = (int)gridDim.x - 1 - (int)blockIdx.x;  // long CTAs first
    const int bh = blockIdx.y;
    const int rb = wid * 16;

    const __half* Qg = g_Qh + ((size_t)bh * Sc + qt * 128) * DKc;
    const __half* Kg = g_Kh + (size_t)bh * Sc * DKc;
    const __half* Vg = g_Vt + (size_t)bh * DKc * Sc;

    const uint32_t smb = smem_u32(smh);
    const uint32_t ksb = smb;
    const uint32_t vtb = smb + 2 * KV_TILE * 2;
    const uint32_t pab = smb + 4 * KV_TILE * 2;
    __half* Pall = smh + 4 * KV_TILE;     // [128][AT]: Q staging then P

    const uint32_t a_off =
        (uint32_t)(((qq & 1) * 8 + rr) * AT + (qq >> 1) * 8) * 2;
    const uint32_t b_off =
        (uint32_t)(((qq >> 1) * 8 + rr) * AT + (qq & 1) * 8) * 2;

    auto load_kv = [&](int kt, int buf) {
#pragma unroll
        for (int i = 0; i < 2; i++) {
            const int ch = tid + i * 256;
            const int r = ch >> 3;
            const int c = ch & 7;
            const uint32_t so = (uint32_t)(buf * KV_TILE + r * AT + c * 8) * 2;
            cp_async16(ksb + so, Kg + ((size_t)(kt * 64 + r)) * DKc + c * 8);
            cp_async16(vtb + so, Vg + (size_t)r * Sc + kt * 64 + c * 8);
        }
        cp_commit();
    };

    // Stage Q
    {
#pragma unroll
        for (int i = 0; i < 4; i++) {
            const int ch = tid + i * 256;
            const int r = ch >> 3;
            const int c = ch & 7;
            cp_async16(pab + (uint32_t)(r * AT + c * 8) * 2,
                       Qg + (size_t)r * DKc + c * 8);
        }
        cp_commit();
    }
    load_kv(0, 0);
    cp_wait<1>();  // Q staged
    __syncthreads();

    uint32_t qf[4][4];
    {
        const uint32_t qbase = pab + (uint32_t)(rb * AT) * 2;
#pragma unroll
        for (int ks = 0; ks < 4; ks++)
            ldm_x4(qf[ks][0], qf[ks][1], qf[ks][2], qf[ks][3],
                   qbase + a_off + ks * 32);
    }

    __half* Pw = Pall + rb * AT;
    uint32_t* Pwu = reinterpret_cast<uint32_t*>(Pw);
    const uint32_t pwbase = pab + (uint32_t)(rb * AT) * 2;

    float m0 = -1e30f, m1 = -1e30f, l0 = 0.0f, l1 = 0.0f;
    float Oacc[8][4] = {};
    const float scale = 0.125f;

    const int ktmax = 2 * qt + 1;
    for (int kt = 0; kt <= ktmax; ++kt) {
        __syncthreads();
        if (kt < ktmax) {
            load_kv(kt + 1, (kt + 1) & 1);
            cp_wait<1>();
        } else {
            cp_wait<0>();
        }
        __syncthreads();

        const int buf = kt & 1;
        const uint32_t kbase = ksb + (uint32_t)(buf * KV_TILE) * 2;
        const uint32_t vbase = vtb + (uint32_t)(buf * KV_TILE) * 2;

        // S = Q @ K^T, pipelined B fragments
        float sacc[8][4] = {};
        {
            uint32_t bf[2][8][2];
#pragma unroll
            for (int p = 0; p < 4; p++)
                ldm_x4(bf[0][2 * p][0], bf[0][2 * p][1], bf[0][2 * p + 1][0],
                       bf[0][2 * p + 1][1],
                       kbase + b_off + (uint32_t)(p * 16 * AT) * 2);
#pragma unroll
            for (int ks = 0; ks < 4; ks++) {
                const int cur = ks & 1;
                const int nxt = cur ^ 1;
                if (ks < 3) {
#pragma unroll
                    for (int p = 0; p < 4; p++)
                        ldm_x4(bf[nxt][2 * p][0], bf[nxt][2 * p][1],
                               bf[nxt][2 * p + 1][0], bf[nxt][2 * p + 1][1],
                               kbase + b_off + (uint32_t)(p * 16 * AT) * 2 +
                                   (ks + 1) * 32);
                }
#pragma unroll
                for (int nt = 0; nt < 8; nt++)
                    mma_f16(sacc[nt], qf[ks], bf[cur][nt]);
            }
        }

        // scale + causal mask
#pragma unroll
        for (int nt = 0; nt < 8; nt++) {
            sacc[nt][0] *= scale;
            sacc[nt][1] *= scale;
            sacc[nt][2] *= scale;
            sacc[nt][3] *= scale;
        }
        if (kt >= 2 * qt) {
            const int cb = kt * 64;
            const int r0g = qt * 128 + rb + g;
            const int r1g = r0g + 8;
#pragma unroll
            for (int nt = 0; nt < 8; nt++) {
                const int c0 = cb + nt * 8 + 2 * t4;
                if (c0 > r0g)     sacc[nt][0] = -1e30f;
                if (c0 + 1 > r0g) sacc[nt][1] = -1e30f;
                if (c0 > r1g)     sacc[nt][2] = -1e30f;
                if (c0 + 1 > r1g) sacc[nt][3] = -1e30f;
            }
        }

        // row max
        float pm0 = -1e30f, pm1 = -1e30f;
#pragma unroll
        for (int nt = 0; nt < 8; nt++) {
            pm0 = fmaxf(pm0, fmaxf(sacc[nt][0], sacc[nt][1]));
            pm1 = fmaxf(pm1, fmaxf(sacc[nt][2], sacc[nt][3]));
        }
        pm0 = fmaxf(pm0, __shfl_xor_sync(0xffffffffu, pm0, 1));
        pm0 = fmaxf(pm0, __shfl_xor_sync(0xffffffffu, pm0, 2));
        pm1 = fmaxf(pm1, __shfl_xor_sync(0xffffffffu, pm1, 1));
        pm1 = fmaxf(pm1, __shfl_xor_sync(0xffffffffu, pm1, 2));

        const float mn0 = fmaxf(m0, pm0);
        const float mn1 = fmaxf(m1, pm1);
        const float a0 = __expf(m0 - mn0);
        const float a1 = __expf(m1 - mn1);
        m0 = mn0;
        m1 = mn1;

        // exp, P write, partial sums
        float ps0 = 0.0f, ps1 = 0.0f;
#pragma unroll
        for (int nt = 0; nt < 8; nt++) {
            const float p0 = __expf(sacc[nt][0] - mn0);
            const float p1 = __expf(sacc[nt][1] - mn0);
            const float p2 = __expf(sacc[nt][2] - mn1);
            const float p3 = __expf(sacc[nt][3] - mn1);
            ps0 += p0 + p1;
            ps1 += p2 + p3;
            Pwu[g * 36 + 4 * nt + t4] = pack_h2(p0, p1);
            Pwu[(g + 8) * 36 + 4 * nt + t4] = pack_h2(p2, p3);
        }
        ps0 += __shfl_xor_sync(0xffffffffu, ps0, 1);
        ps0 += __shfl_xor_sync(0xffffffffu, ps0, 2);
        ps1 += __shfl_xor_sync(0xffffffffu, ps1, 1);
        ps1 += __shfl_xor_sync(0xffffffffu, ps1, 2);
        l0 = l0 * a0 + ps0;
        l1 = l1 * a1 + ps1;

#pragma unroll
        for (int nt = 0; nt < 8; nt++) {
            Oacc[nt][0] *= a0;
            Oacc[nt][1] *= a0;
            Oacc[nt][2] *= a1;
            Oacc[nt][3] *= a1;
        }
        __syncwarp();

        // O += P @ V, pipelined A+B fragments
        {
            uint32_t af[2][4], bf[2][8][2];
            ldm_x4(af[0][0], af[0][1], af[0][2], af[0][3], pwbase + a_off);
#pragma unroll
            for (int p = 0; p < 4; p++)
                ldm_x4(bf[0][2 * p][0], bf[0][2 * p][1], bf[0][2 * p + 1][0],
                       bf[0][2 * p + 1][1],
                       vbase + b_off + (uint32_t)(p * 16 * AT) * 2);
#pragma unroll
            for (int ks = 0; ks < 4; ks++) {
                const int cur = ks & 1;
                const int nxt = cur ^ 1;
                if (ks < 3) {
                    ldm_x4(af[nxt][0], af[nxt][1], af[nxt][2], af[nxt][3],
                           pwbase + a_off + (ks + 1) * 32);
#pragma unroll
                    for (int p = 0; p < 4; p++)
                        ldm_x4(bf[nxt][2 * p][0], bf[nxt][2 * p][1],
                               bf[nxt][2 * p + 1][0], bf[nxt][2 * p + 1][1],
                               vbase + b_off + (uint32_t)(p * 16 * AT) * 2 +
                                   (ks + 1) * 32);
                }
#pragma unroll
                for (int nt = 0; nt < 8; nt++)
                    mma_f16(Oacc[nt], af[cur], bf[cur][nt]);
            }
        }
        __syncwarp();
    }

    // Epilogue
    const int b = bh >> 4;
    const int h = bh & 15;
    const float inv0 = 1.0f / l0;
    const float inv1 = 1.0f / l1;
    const int s0 = qt * 128 + rb + g;
    const int s1 = s0 + 8;
#pragma unroll
    for (int nt = 0; nt < 8; nt++) {
        const int c = nt * 8 + 2 * t4;
        __half2 o0 = __floats2half2_rn(Oacc[nt][0] * inv0, Oacc[nt][1] * inv0);
        __half2 o1 = __floats2half2_rn(Oacc[nt][2] * inv1, Oacc[nt][3] * inv1);
        *reinterpret_cast<__half2*>(g_att + ((size_t)(b * Sc + s0)) * Dc + h * 64 + c) = o0;
        *reinterpret_cast<__half2*>(g_att + ((size_t)(b * Sc + s1)) * Dc + h * 64 + c) = o1;
    }
}

// ---------------------------------------------------------------------------
extern "C" void kernel_launch(void* const* d_in, const int* in_sizes, int n_in,
                              void* d_out, int out_size) {
    const float* q  = (const float*)d_in[0];
    const float* k  = (const float*)d_in[1];
    const float* v  = (const float*)d_in[2];
    // d_in[3] = mask (causal implemented directly)
    const float* Wq = (const float*)d_in[4];
    const float* bq = (const float*)d_in[5];
    const float* Wk = (const float*)d_in[6];
    const float* bk = (const float*)d_in[7];
    const float* Wv = (const float*)d_in[8];
    const float* bv = (const float*)d_in[9];
    const float* Wo = (const float*)d_in[10];
    const float* bo = (const float*)d_in[11];
    float* out = (float*)d_out;

    cudaFuncSetAttribute(proj_qkv_kernel,
                         cudaFuncAttributeMaxDynamicSharedMemorySize, PROJ_SMEM);
    cudaFuncSetAttribute(proj_o_kernel,
                         cudaFuncAttributeMaxDynamicSharedMemorySize, PROJ_SMEM);
    cudaFuncSetAttribute(attn_kernel,
                         cudaFuncAttributeMaxDynamicSharedMemorySize, ATTN_SMEM_BYTES);

    cvt_kernel<<<2048, 256>>>(q, k, v, Wq, Wk, Wv, Wo);

    dim3 qkvgrid(Dc / 128, Mc / 128, 3);  // (8, 32, 3)
    proj_qkv_kernel<<<qkvgrid, 256, PROJ_SMEM>>>(bq, bk, bv);

    dim3 agrid(Sc / 128, Bc * Hc);        // (16, 32)
    attn_kernel<<<agrid, 256, ATTN_SMEM_BYTES>>>(out);

    dim3 ogrid(Dc / 128, Mc / 128);       // (8, 32)
    proj_o_kernel<<<ogrid, 256, PROJ_SMEM>>>(bo, out);
}

// round 16
// speedup vs baseline: 1.0593x; 1.0593x over previous
#include <cuda_runtime.h>
#include <cuda_fp16.h>
#include <cstdint>

// Problem constants
constexpr int Bc = 2;
constexpr int Sc = 2048;
constexpr int Dc = 1024;
constexpr int Hc = 16;
constexpr int DKc = 64;
constexpr int Mc = Bc * Sc;  // 4096

// Half scratch (device globals: allocation-free)
__device__ __half g_q16[(size_t)Mc * Dc];
__device__ __half g_k16[(size_t)Mc * Dc];
__device__ __half g_v16[(size_t)Mc * Dc];
__device__ __half g_Wq16[(size_t)Dc * Dc];
__device__ __half g_Wk16[(size_t)Dc * Dc];
__device__ __half g_Wv16[(size_t)Dc * Dc];
__device__ __half g_Wo16[(size_t)Dc * Dc];
__device__ __half g_Qh[(size_t)Bc * Hc * Sc * DKc];   // [b,h,s,dk]
__device__ __half g_Kh[(size_t)Bc * Hc * Sc * DKc];   // [b,h,s,dk]
__device__ __half g_Vt[(size_t)Bc * Hc * DKc * Sc];   // [b,h,dk,s] (transposed)
__device__ __half g_att[(size_t)Mc * Dc];             // [b,s,d]

// ---------------------------------------------------------------------------
// Helpers
// ---------------------------------------------------------------------------
__device__ __forceinline__ uint32_t smem_u32(const void* p) {
    uint32_t a;
    asm("{ .reg .u64 t; cvta.to.shared.u64 t, %1; cvt.u32.u64 %0, t; }"
        : "=r"(a) : "l"(p));
    return a;
}
__device__ __forceinline__ void cp_async16(uint32_t s, const void* g) {
    asm volatile("cp.async.cg.shared.global [%0], [%1], 16;" :: "r"(s), "l"(g));
}
__device__ __forceinline__ void cp_commit() {
    asm volatile("cp.async.commit_group;" ::: "memory");
}
template <int N>
__device__ __forceinline__ void cp_wait() {
    asm volatile("cp.async.wait_group %0;" :: "n"(N) : "memory");
}
__device__ __forceinline__ uint32_t pack_h2(float a, float b) {
    __half2 h = __floats2half2_rn(a, b);
    return *reinterpret_cast<uint32_t*>(&h);
}
__device__ __forceinline__ void mma_f16(float* C, const uint32_t* A,
                                        const uint32_t* B) {
    asm volatile(
        "mma.sync.aligned.m16n8k16.row.col.f32.f16.f16.f32 "
        "{%0,%1,%2,%3}, {%4,%5,%6,%7}, {%8,%9}, {%0,%1,%2,%3};"
        : "+f"(C[0]), "+f"(C[1]), "+f"(C[2]), "+f"(C[3])
        : "r"(A[0]), "r"(A[1]), "r"(A[2]), "r"(A[3]), "r"(B[0]), "r"(B[1]));
}
__device__ __forceinline__ void ldm_x4(uint32_t& r0, uint32_t& r1, uint32_t& r2,
                                       uint32_t& r3, uint32_t addr) {
    asm volatile("ldmatrix.sync.aligned.m8n8.x4.shared.b16 {%0,%1,%2,%3}, [%4];"
                 : "=r"(r0), "=r"(r1), "=r"(r2), "=r"(r3) : "r"(addr));
}

// ---------------------------------------------------------------------------
// Prepass: fp32 -> fp16 conversion of inputs + weights.
// ---------------------------------------------------------------------------
__global__ void __launch_bounds__(256) cvt_kernel(const float* __restrict__ q,
                                                  const float* __restrict__ k,
                                                  const float* __restrict__ v,
                                                  const float* __restrict__ Wq,
                                                  const float* __restrict__ Wk,
                                                  const float* __restrict__ Wv,
                                                  const float* __restrict__ Wo) {
    constexpr size_t NIN = 1048576;   // float4 per input
    constexpr size_t NW = 262144;     // float4 per weight
    const size_t total = 3 * NIN + 4 * NW;
    for (size_t idx = blockIdx.x * 256 + threadIdx.x; idx < total;
         idx += (size_t)gridDim.x * 256) {
        const float* src;
        __half* dst;
        size_t off;
        if (idx < 3 * NIN) {
            const int w = (int)(idx / NIN);
            off = idx % NIN;
            src = (w == 0) ? q : (w == 1) ? k : v;
            dst = (w == 0) ? g_q16 : (w == 1) ? g_k16 : g_v16;
        } else {
            const size_t r = idx - 3 * NIN;
            const int w = (int)(r / NW);
            off = r % NW;
            src = (w == 0) ? Wq : (w == 1) ? Wk : (w == 2) ? Wv : Wo;
            dst = (w == 0) ? g_Wq16 : (w == 1) ? g_Wk16 : (w == 2) ? g_Wv16 : g_Wo16;
        }
        float4 f = reinterpret_cast<const float4*>(src)[off];
        uint2 u;
        u.x = pack_h2(f.x, f.y);
        u.y = pack_h2(f.z, f.w);
        reinterpret_cast<uint2*>(dst)[off] = u;
    }
}

// ---------------------------------------------------------------------------
// fp16 projection GEMM, ldmatrix fragments, 3-stage cp.async ring with ONE
// barrier per k-block. CTA 128x128, BK=64 halfs, 8 warps (4m x 2n).
// ---------------------------------------------------------------------------
constexpr int PBKH = 64;
constexpr int PSTRH = 72;
constexpr int PTILEH = 128 * PSTRH;
constexpr int PSTAGES = 3;
constexpr int PROJ_SMEM = PSTAGES * 2 * PTILEH * 2;  // 110592 B

template <int MODE>
__device__ __forceinline__ void proj_body(const __half* __restrict__ A,
                                          const __half* __restrict__ W,
                                          const float* __restrict__ bias,
                                          void* __restrict__ outp,
                                          __half* sm, int row0, int col0) {
    const uint32_t smb = smem_u32(sm);
    const int tid = threadIdx.x;
    const int wid = tid >> 5;
    const int lid = tid & 31;
    const int g = lid >> 2;
    const int t4 = lid & 3;
    const int wm = wid & 3;
    const int wn = wid >> 2;
    const int qq = lid >> 3;
    const int rr = lid & 7;

    const uint32_t aoff =
        (uint32_t)((wm * 32 + (qq & 1) * 8 + rr) * PSTRH + (qq >> 1) * 8) * 2;
    const uint32_t boff =
        (uint32_t)((wn * 64 + (qq >> 1) * 8 + rr) * PSTRH + (qq & 1) * 8) * 2;

    const __half* Ap = A + (size_t)row0 * Dc;
    const __half* Wp = W + (size_t)col0 * Dc;

    auto load_tiles = [&](int kb, int stage) {
        const int k0 = kb * PBKH;
        const uint32_t abase = smb + (uint32_t)(stage * 2 * PTILEH) * 2;
        const uint32_t bbase = abase + (uint32_t)PTILEH * 2;
#pragma unroll
        for (int i = 0; i < 4; i++) {
            const int ch = tid + i * 256;
            const int r = ch >> 3;
            const int c = ch & 7;
            const uint32_t so = (uint32_t)(r * PSTRH + c * 8) * 2;
            cp_async16(abase + so, Ap + (size_t)r * Dc + k0 + c * 8);
            cp_async16(bbase + so, Wp + (size_t)r * Dc + k0 + c * 8);
        }
        cp_commit();
    };

    float acc[2][8][4] = {};

    const int NKB = Dc / PBKH;  // 16
    load_tiles(0, 0);
    load_tiles(1, 1);
    int stage = 0;
    for (int kb = 0; kb < NKB; kb++) {
        if (kb < NKB - 1) {
            cp_wait<1>();   // stage for kb complete
        } else {
            cp_wait<0>();
        }
        __syncthreads();    // publish tile kb; all warps done with tile kb-1
        if (kb + 2 < NKB) {
            load_tiles(kb + 2, (stage + 2 >= PSTAGES) ? stage + 2 - PSTAGES
                                                      : stage + 2);
        }

        const uint32_t abase = smb + (uint32_t)(stage * 2 * PTILEH) * 2;
        const uint32_t bbase = abase + (uint32_t)PTILEH * 2;
#pragma unroll
        for (int ks = 0; ks < 4; ks++) {
            uint32_t af[2][4];
            ldm_x4(af[0][0], af[0][1], af[0][2], af[0][3],
                   abase + aoff + ks * 32);
            ldm_x4(af[1][0], af[1][1], af[1][2], af[1][3],
                   abase + aoff + 16 * PSTRH * 2 + ks * 32);
            uint32_t bf[8][2];
#pragma unroll
            for (int p = 0; p < 4; p++) {
                ldm_x4(bf[2 * p][0], bf[2 * p][1], bf[2 * p + 1][0],
                       bf[2 * p + 1][1],
                       bbase + boff + (uint32_t)(p * 16 * PSTRH) * 2 + ks * 32);
            }
#pragma unroll
            for (int nt = 0; nt < 8; nt++)
#pragma unroll
                for (int mt = 0; mt < 2; mt++)
                    mma_f16(acc[mt][nt], af[mt], bf[nt]);
        }
        stage = (stage + 1 == PSTAGES) ? 0 : stage + 1;
    }

    // Epilogue
#pragma unroll
    for (int mt = 0; mt < 2; mt++) {
#pragma unroll
        for (int half_ = 0; half_ < 2; half_++) {
            const int m = row0 + wm * 32 + mt * 16 + g + half_ * 8;
            const int b = m >> 11;
            const int s = m & 2047;
#pragma unroll
            for (int nt = 0; nt < 8; nt++) {
                const int n = col0 + wn * 64 + nt * 8 + t4 * 2;
                const float ox = acc[mt][nt][half_ * 2 + 0] + bias[n];
                const float oy = acc[mt][nt][half_ * 2 + 1] + bias[n + 1];
                if (MODE == 0) {
                    float2 o = {ox, oy};
                    *reinterpret_cast<float2*>((float*)outp + (size_t)m * Dc + n) = o;
                } else if (MODE == 1) {
                    const int h = n >> 6, dk = n & 63;
                    __half2 o = __floats2half2_rn(ox, oy);
                    *reinterpret_cast<__half2*>(
                        (__half*)outp + ((size_t)((b * Hc + h) * Sc + s) << 6) + dk) = o;
                } else {
                    const int h = n >> 6, dk = n & 63;
                    __half* dst = (__half*)outp +
                                  ((size_t)((b * Hc + h) * DKc + dk)) * Sc + s;
                    dst[0] = __float2half_rn(ox);
                    dst[Sc] = __float2half_rn(oy);
                }
            }
        }
    }
}

__global__ void __launch_bounds__(256) proj_qkv_kernel(
    const float* __restrict__ bq, const float* __restrict__ bk,
    const float* __restrict__ bv) {
    extern __shared__ __half smh[];
    const int z = blockIdx.z;
    const int row0 = blockIdx.y * 128, col0 = blockIdx.x * 128;
    if (z == 0) {
        proj_body<1>(g_q16, g_Wq16, bq, g_Qh, smh, row0, col0);
    } else if (z == 1) {
        proj_body<1>(g_k16, g_Wk16, bk, g_Kh, smh, row0, col0);
    } else {
        proj_body<2>(g_v16, g_Wv16, bv, g_Vt, smh, row0, col0);
    }
}

__global__ void __launch_bounds__(256) proj_o_kernel(const float* __restrict__ bo,
                                                     float* __restrict__ out) {
    extern __shared__ __half smh[];
    proj_body<0>(g_att, g_Wo16, bo, out, smh, blockIdx.y * 128, blockIdx.x * 128);
}

// ---------------------------------------------------------------------------
// Flash attention (causal), fp16 mma + ldmatrix, double-buffered K/V with ONE
// barrier per kt iteration, reversed-qt schedule. 8 warps x 16 rows.
// ---------------------------------------------------------------------------
constexpr int AT = 72;            // half stride (36 words)
constexpr int KV_TILE = 64 * AT;  // halfs
constexpr int ATTN_SMEM_HALFS = 2 * KV_TILE + 2 * KV_TILE + 128 * AT;
constexpr int ATTN_SMEM_BYTES = ATTN_SMEM_HALFS * 2;  // 55296

__global__ void __launch_bounds__(256, 2) attn_kernel(float* /*unused*/) {
    extern __shared__ __half smh[];

    const int tid = threadIdx.x;
    const int wid = tid >> 5;
    const int lid = tid & 31;
    const int g = lid >> 2;
    const int t4 = lid & 3;
    const int qq = lid >> 3;
    const int rr = lid & 7;
    const int qt = (int)gridDim.x - 1 - (int)blockIdx.x;  // long CTAs first
    const int bh = blockIdx.y;
    const int rb = wid * 16;

    const __half* Qg = g_Qh + ((size_t)bh * Sc + qt * 128) * DKc;
    const __half* Kg = g_Kh + (size_t)bh * Sc * DKc;
    const __half* Vg = g_Vt + (size_t)bh * DKc * Sc;

    const uint32_t smb = smem_u32(smh);
    const uint32_t ksb = smb;
    const uint32_t vtb = smb + 2 * KV_TILE * 2;
    const uint32_t pab = smb + 4 * KV_TILE * 2;
    __half* Pall = smh + 4 * KV_TILE;     // [128][AT]: Q staging then P

    const uint32_t a_off =
        (uint32_t)(((qq & 1) * 8 + rr) * AT + (qq >> 1) * 8) * 2;
    const uint32_t b_off =
        (uint32_t)(((qq >> 1) * 8 + rr) * AT + (qq & 1) * 8) * 2;

    auto load_kv = [&](int kt, int buf) {
#pragma unroll
        for (int i = 0; i < 2; i++) {
            const int ch = tid + i * 256;
            const int r = ch >> 3;
            const int c = ch & 7;
            const uint32_t so = (uint32_t)(buf * KV_TILE + r * AT + c * 8) * 2;
            cp_async16(ksb + so, Kg + ((size_t)(kt * 64 + r)) * DKc + c * 8);
            cp_async16(vtb + so, Vg + (size_t)r * Sc + kt * 64 + c * 8);
        }
        cp_commit();
    };

    // Stage Q
    {
#pragma unroll
        for (int i = 0; i < 4; i++) {
            const int ch = tid + i * 256;
            const int r = ch >> 3;
            const int c = ch & 7;
            cp_async16(pab + (uint32_t)(r * AT + c * 8) * 2,
                       Qg + (size_t)r * DKc + c * 8);
        }
        cp_commit();
    }
    load_kv(0, 0);
    cp_wait<1>();  // Q staged (kv0 may still be in flight)
    __syncthreads();

    uint32_t qf[4][4];
    {
        const uint32_t qbase = pab + (uint32_t)(rb * AT) * 2;
#pragma unroll
        for (int ks = 0; ks < 4; ks++)
            ldm_x4(qf[ks][0], qf[ks][1], qf[ks][2], qf[ks][3],
                   qbase + a_off + ks * 32);
    }

    __half* Pw = Pall + rb * AT;
    uint32_t* Pwu = reinterpret_cast<uint32_t*>(Pw);
    const uint32_t pwbase = pab + (uint32_t)(rb * AT) * 2;

    float m0 = -1e30f, m1 = -1e30f, l0 = 0.0f, l1 = 0.0f;
    float Oacc[8][4] = {};
    const float scale = 0.125f;

    const int ktmax = 2 * qt + 1;
    for (int kt = 0; kt <= ktmax; ++kt) {
        cp_wait<0>();      // K/V tile kt complete
        __syncthreads();   // publish kt; all warps done with tile kt-1
        if (kt < ktmax) load_kv(kt + 1, (kt + 1) & 1);

        const int buf = kt & 1;
        const uint32_t kbase = ksb + (uint32_t)(buf * KV_TILE) * 2;
        const uint32_t vbase = vtb + (uint32_t)(buf * KV_TILE) * 2;

        // S = Q @ K^T
        float sacc[8][4] = {};
#pragma unroll
        for (int ks = 0; ks < 4; ks++) {
            uint32_t bf[8][2];
#pragma unroll
            for (int p = 0; p < 4; p++) {
                ldm_x4(bf[2 * p][0], bf[2 * p][1], bf[2 * p + 1][0],
                       bf[2 * p + 1][1],
                       kbase + b_off + (uint32_t)(p * 16 * AT) * 2 + ks * 32);
            }
#pragma unroll
            for (int nt = 0; nt < 8; nt++) mma_f16(sacc[nt], qf[ks], bf[nt]);
        }

        // scale + causal mask
#pragma unroll
        for (int nt = 0; nt < 8; nt++) {
            sacc[nt][0] *= scale;
            sacc[nt][1] *= scale;
            sacc[nt][2] *= scale;
            sacc[nt][3] *= scale;
        }
        if (kt >= 2 * qt) {
            const int cb = kt * 64;
            const int r0g = qt * 128 + rb + g;
            const int r1g = r0g + 8;
#pragma unroll
            for (int nt = 0; nt < 8; nt++) {
                const int c0 = cb + nt * 8 + 2 * t4;
                if (c0 > r0g)     sacc[nt][0] = -1e30f;
                if (c0 + 1 > r0g) sacc[nt][1] = -1e30f;
                if (c0 > r1g)     sacc[nt][2] = -1e30f;
                if (c0 + 1 > r1g) sacc[nt][3] = -1e30f;
            }
        }

        // row max
        float pm0 = -1e30f, pm1 = -1e30f;
#pragma unroll
        for (int nt = 0; nt < 8; nt++) {
            pm0 = fmaxf(pm0, fmaxf(sacc[nt][0], sacc[nt][1]));
            pm1 = fmaxf(pm1, fmaxf(sacc[nt][2], sacc[nt][3]));
        }
        pm0 = fmaxf(pm0, __shfl_xor_sync(0xffffffffu, pm0, 1));
        pm0 = fmaxf(pm0, __shfl_xor_sync(0xffffffffu, pm0, 2));
        pm1 = fmaxf(pm1, __shfl_xor_sync(0xffffffffu, pm1, 1));
        pm1 = fmaxf(pm1, __shfl_xor_sync(0xffffffffu, pm1, 2));

        const float mn0 = fmaxf(m0, pm0);
        const float mn1 = fmaxf(m1, pm1);
        const float a0 = __expf(m0 - mn0);
        const float a1 = __expf(m1 - mn1);
        m0 = mn0;
        m1 = mn1;

        // exp, P write, partial sums
        float ps0 = 0.0f, ps1 = 0.0f;
#pragma unroll
        for (int nt = 0; nt < 8; nt++) {
            const float p0 = __expf(sacc[nt][0] - mn0);
            const float p1 = __expf(sacc[nt][1] - mn0);
            const float p2 = __expf(sacc[nt][2] - mn1);
            const float p3 = __expf(sacc[nt][3] - mn1);
            ps0 += p0 + p1;
            ps1 += p2 + p3;
            Pwu[g * 36 + 4 * nt + t4] = pack_h2(p0, p1);
            Pwu[(g + 8) * 36 + 4 * nt + t4] = pack_h2(p2, p3);
        }
        ps0 += __shfl_xor_sync(0xffffffffu, ps0, 1);
        ps0 += __shfl_xor_sync(0xffffffffu, ps0, 2);
        ps1 += __shfl_xor_sync(0xffffffffu, ps1, 1);
        ps1 += __shfl_xor_sync(0xffffffffu, ps1, 2);
        l0 = l0 * a0 + ps0;
        l1 = l1 * a1 + ps1;

#pragma unroll
        for (int nt = 0; nt < 8; nt++) {
            Oacc[nt][0] *= a0;
            Oacc[nt][1] *= a0;
            Oacc[nt][2] *= a1;
            Oacc[nt][3] *= a1;
        }
        __syncwarp();

        // O += P @ V
#pragma unroll
        for (int ks = 0; ks < 4; ks++) {
            uint32_t af[4];
            ldm_x4(af[0], af[1], af[2], af[3], pwbase + a_off + ks * 32);
            uint32_t bf[8][2];
#pragma unroll
            for (int p = 0; p < 4; p++) {
                ldm_x4(bf[2 * p][0], bf[2 * p][1], bf[2 * p + 1][0],
                       bf[2 * p + 1][1],
                       vbase + b_off + (uint32_t)(p * 16 * AT) * 2 + ks * 32);
            }
#pragma unroll
            for (int nt = 0; nt < 8; nt++) mma_f16(Oacc[nt], af, bf[nt]);
        }
        __syncwarp();
    }

    // Epilogue
    const int b = bh >> 4;
    const int h = bh & 15;
    const float inv0 = 1.0f / l0;
    const float inv1 = 1.0f / l1;
    const int s0 = qt * 128 + rb + g;
    const int s1 = s0 + 8;
#pragma unroll
    for (int nt = 0; nt < 8; nt++) {
        const int c = nt * 8 + 2 * t4;
        __half2 o0 = __floats2half2_rn(Oacc[nt][0] * inv0, Oacc[nt][1] * inv0);
        __half2 o1 = __floats2half2_rn(Oacc[nt][2] * inv1, Oacc[nt][3] * inv1);
        *reinterpret_cast<__half2*>(g_att + ((size_t)(b * Sc + s0)) * Dc + h * 64 + c) = o0;
        *reinterpret_cast<__half2*>(g_att + ((size_t)(b * Sc + s1)) * Dc + h * 64 + c) = o1;
    }
}

// ---------------------------------------------------------------------------
extern "C" void kernel_launch(void* const* d_in, const int* in_sizes, int n_in,
                              void* d_out, int out_size) {
    const float* q  = (const float*)d_in[0];
    const float* k  = (const float*)d_in[1];
    const float* v  = (const float*)d_in[2];
    // d_in[3] = mask (causal implemented directly)
    const float* Wq = (const float*)d_in[4];
    const float* bq = (const float*)d_in[5];
    const float* Wk = (const float*)d_in[6];
    const float* bk = (const float*)d_in[7];
    const float* Wv = (const float*)d_in[8];
    const float* bv = (const float*)d_in[9];
    const float* Wo = (const float*)d_in[10];
    const float* bo = (const float*)d_in[11];
    float* out = (float*)d_out;

    cudaFuncSetAttribute(proj_qkv_kernel,
                         cudaFuncAttributeMaxDynamicSharedMemorySize, PROJ_SMEM);
    cudaFuncSetAttribute(proj_o_kernel,
                         cudaFuncAttributeMaxDynamicSharedMemorySize, PROJ_SMEM);
    cudaFuncSetAttribute(attn_kernel,
                         cudaFuncAttributeMaxDynamicSharedMemorySize, ATTN_SMEM_BYTES);

    cvt_kernel<<<2048, 256>>>(q, k, v, Wq, Wk, Wv, Wo);

    dim3 qkvgrid(Dc / 128, Mc / 128, 3);  // (8, 32, 3)
    proj_qkv_kernel<<<qkvgrid, 256, PROJ_SMEM>>>(bq, bk, bv);

    dim3 agrid(Sc / 128, Bc * Hc);        // (16, 32)
    attn_kernel<<<agrid, 256, ATTN_SMEM_BYTES>>>(out);

    dim3 ogrid(Dc / 128, Mc / 128);       // (8, 32)
    proj_o_kernel<<<ogrid, 256, PROJ_SMEM>>>(bo, out);
}

// round 17
// speedup vs baseline: 1.0607x; 1.0013x over previous
#include <cuda_runtime.h>
#include <cuda_fp16.h>
#include <cstdint>

// Problem constants
constexpr int Bc = 2;
constexpr int Sc = 2048;
constexpr int Dc = 1024;
constexpr int Hc = 16;
constexpr int DKc = 64;
constexpr int Mc = Bc * Sc;  // 4096

// Half scratch (device globals: allocation-free)
__device__ __half g_q16[(size_t)Mc * Dc];
__device__ __half g_k16[(size_t)Mc * Dc];
__device__ __half g_v16[(size_t)Mc * Dc];
__device__ __half g_Wq16[(size_t)Dc * Dc];
__device__ __half g_Wk16[(size_t)Dc * Dc];
__device__ __half g_Wv16[(size_t)Dc * Dc];
__device__ __half g_Wo16[(size_t)Dc * Dc];
__device__ __half g_Qh[(size_t)Bc * Hc * Sc * DKc];   // [b,h,s,dk]
__device__ __half g_Kh[(size_t)Bc * Hc * Sc * DKc];   // [b,h,s,dk]
__device__ __half g_Vt[(size_t)Bc * Hc * DKc * Sc];   // [b,h,dk,s] (transposed)
__device__ __half g_att[(size_t)Mc * Dc];             // [b,s,d]

// ---------------------------------------------------------------------------
// Helpers
// ---------------------------------------------------------------------------
__device__ __forceinline__ uint32_t smem_u32(const void* p) {
    uint32_t a;
    asm("{ .reg .u64 t; cvta.to.shared.u64 t, %1; cvt.u32.u64 %0, t; }"
        : "=r"(a) : "l"(p));
    return a;
}
__device__ __forceinline__ void cp_async16(uint32_t s, const void* g) {
    asm volatile("cp.async.cg.shared.global [%0], [%1], 16;" :: "r"(s), "l"(g));
}
__device__ __forceinline__ void cp_commit() {
    asm volatile("cp.async.commit_group;" ::: "memory");
}
template <int N>
__device__ __forceinline__ void cp_wait() {
    asm volatile("cp.async.wait_group %0;" :: "n"(N) : "memory");
}
__device__ __forceinline__ uint32_t pack_h2(float a, float b) {
    __half2 h = __floats2half2_rn(a, b);
    return *reinterpret_cast<uint32_t*>(&h);
}
__device__ __forceinline__ void mma_f16(float* C, const uint32_t* A,
                                        const uint32_t* B) {
    asm volatile(
        "mma.sync.aligned.m16n8k16.row.col.f32.f16.f16.f32 "
        "{%0,%1,%2,%3}, {%4,%5,%6,%7}, {%8,%9}, {%0,%1,%2,%3};"
        : "+f"(C[0]), "+f"(C[1]), "+f"(C[2]), "+f"(C[3])
        : "r"(A[0]), "r"(A[1]), "r"(A[2]), "r"(A[3]), "r"(B[0]), "r"(B[1]));
}
__device__ __forceinline__ void ldm_x4(uint32_t& r0, uint32_t& r1, uint32_t& r2,
                                       uint32_t& r3, uint32_t addr) {
    asm volatile("ldmatrix.sync.aligned.m8n8.x4.shared.b16 {%0,%1,%2,%3}, [%4];"
                 : "=r"(r0), "=r"(r1), "=r"(r2), "=r"(r3) : "r"(addr));
}

// ---------------------------------------------------------------------------
// Prepass: fp32 -> fp16 conversion of inputs + weights.
// ---------------------------------------------------------------------------
__global__ void __launch_bounds__(256) cvt_kernel(const float* __restrict__ q,
                                                  const float* __restrict__ k,
                                                  const float* __restrict__ v,
                                                  const float* __restrict__ Wq,
                                                  const float* __restrict__ Wk,
                                                  const float* __restrict__ Wv,
                                                  const float* __restrict__ Wo) {
    constexpr size_t NIN = 1048576;   // float4 per input
    constexpr size_t NW = 262144;     // float4 per weight
    const size_t total = 3 * NIN + 4 * NW;
    for (size_t idx = blockIdx.x * 256 + threadIdx.x; idx < total;
         idx += (size_t)gridDim.x * 256) {
        const float* src;
        __half* dst;
        size_t off;
        if (idx < 3 * NIN) {
            const int w = (int)(idx / NIN);
            off = idx % NIN;
            src = (w == 0) ? q : (w == 1) ? k : v;
            dst = (w == 0) ? g_q16 : (w == 1) ? g_k16 : g_v16;
        } else {
            const size_t r = idx - 3 * NIN;
            const int w = (int)(r / NW);
            off = r % NW;
            src = (w == 0) ? Wq : (w == 1) ? Wk : (w == 2) ? Wv : Wo;
            dst = (w == 0) ? g_Wq16 : (w == 1) ? g_Wk16 : (w == 2) ? g_Wv16 : g_Wo16;
        }
        float4 f = reinterpret_cast<const float4*>(src)[off];
        uint2 u;
        u.x = pack_h2(f.x, f.y);
        u.y = pack_h2(f.z, f.w);
        reinterpret_cast<uint2*>(dst)[off] = u;
    }
}

// ---------------------------------------------------------------------------
// fp16 projection GEMM, ldmatrix fragments, 3-stage cp.async ring with ONE
// barrier per k-block. CTA 128x128, BK=64 halfs, 8 warps (4m x 2n).
// ---------------------------------------------------------------------------
constexpr int PBKH = 64;
constexpr int PSTRH = 72;
constexpr int PTILEH = 128 * PSTRH;
constexpr int PSTAGES = 3;
constexpr int PROJ_SMEM = PSTAGES * 2 * PTILEH * 2;  // 110592 B

template <int MODE>
__device__ __forceinline__ void proj_body(const __half* __restrict__ A,
                                          const __half* __restrict__ W,
                                          const float* __restrict__ bias,
                                          void* __restrict__ outp,
                                          __half* sm, int row0, int col0) {
    const uint32_t smb = smem_u32(sm);
    const int tid = threadIdx.x;
    const int wid = tid >> 5;
    const int lid = tid & 31;
    const int g = lid >> 2;
    const int t4 = lid & 3;
    const int wm = wid & 3;
    const int wn = wid >> 2;
    const int qq = lid >> 3;
    const int rr = lid & 7;

    const uint32_t aoff =
        (uint32_t)((wm * 32 + (qq & 1) * 8 + rr) * PSTRH + (qq >> 1) * 8) * 2;
    const uint32_t boff =
        (uint32_t)((wn * 64 + (qq >> 1) * 8 + rr) * PSTRH + (qq & 1) * 8) * 2;

    const __half* Ap = A + (size_t)row0 * Dc;
    const __half* Wp = W + (size_t)col0 * Dc;

    auto load_tiles = [&](int kb, int stage) {
        const int k0 = kb * PBKH;
        const uint32_t abase = smb + (uint32_t)(stage * 2 * PTILEH) * 2;
        const uint32_t bbase = abase + (uint32_t)PTILEH * 2;
#pragma unroll
        for (int i = 0; i < 4; i++) {
            const int ch = tid + i * 256;
            const int r = ch >> 3;
            const int c = ch & 7;
            const uint32_t so = (uint32_t)(r * PSTRH + c * 8) * 2;
            cp_async16(abase + so, Ap + (size_t)r * Dc + k0 + c * 8);
            cp_async16(bbase + so, Wp + (size_t)r * Dc + k0 + c * 8);
        }
        cp_commit();
    };

    float acc[2][8][4] = {};

    const int NKB = Dc / PBKH;  // 16
    load_tiles(0, 0);
    load_tiles(1, 1);
    int stage = 0;
    for (int kb = 0; kb < NKB; kb++) {
        if (kb < NKB - 1) {
            cp_wait<1>();   // stage for kb complete
        } else {
            cp_wait<0>();
        }
        __syncthreads();    // publish tile kb; all warps done with tile kb-1
        if (kb + 2 < NKB) {
            load_tiles(kb + 2, (stage + 2 >= PSTAGES) ? stage + 2 - PSTAGES
                                                      : stage + 2);
        }

        const uint32_t abase = smb + (uint32_t)(stage * 2 * PTILEH) * 2;
        const uint32_t bbase = abase + (uint32_t)PTILEH * 2;
#pragma unroll
        for (int ks = 0; ks < 4; ks++) {
            uint32_t af[2][4];
            ldm_x4(af[0][0], af[0][1], af[0][2], af[0][3],
                   abase + aoff + ks * 32);
            ldm_x4(af[1][0], af[1][1], af[1][2], af[1][3],
                   abase + aoff + 16 * PSTRH * 2 + ks * 32);
            uint32_t bf[8][2];
#pragma unroll
            for (int p = 0; p < 4; p++) {
                ldm_x4(bf[2 * p][0], bf[2 * p][1], bf[2 * p + 1][0],
                       bf[2 * p + 1][1],
                       bbase + boff + (uint32_t)(p * 16 * PSTRH) * 2 + ks * 32);
            }
#pragma unroll
            for (int nt = 0; nt < 8; nt++)
#pragma unroll
                for (int mt = 0; mt < 2; mt++)
                    mma_f16(acc[mt][nt], af[mt], bf[nt]);
        }
        stage = (stage + 1 == PSTAGES) ? 0 : stage + 1;
    }

    // Epilogue
#pragma unroll
    for (int mt = 0; mt < 2; mt++) {
#pragma unroll
        for (int half_ = 0; half_ < 2; half_++) {
            const int m = row0 + wm * 32 + mt * 16 + g + half_ * 8;
            const int b = m >> 11;
            const int s = m & 2047;
#pragma unroll
            for (int nt = 0; nt < 8; nt++) {
                const int n = col0 + wn * 64 + nt * 8 + t4 * 2;
                const float ox = acc[mt][nt][half_ * 2 + 0] + bias[n];
                const float oy = acc[mt][nt][half_ * 2 + 1] + bias[n + 1];
                if (MODE == 0) {
                    float2 o = {ox, oy};
                    *reinterpret_cast<float2*>((float*)outp + (size_t)m * Dc + n) = o;
                } else if (MODE == 1) {
                    const int h = n >> 6, dk = n & 63;
                    __half2 o = __floats2half2_rn(ox, oy);
                    *reinterpret_cast<__half2*>(
                        (__half*)outp + ((size_t)((b * Hc + h) * Sc + s) << 6) + dk) = o;
                } else {
                    const int h = n >> 6, dk = n & 63;
                    __half* dst = (__half*)outp +
                                  ((size_t)((b * Hc + h) * DKc + dk)) * Sc + s;
                    dst[0] = __float2half_rn(ox);
                    dst[Sc] = __float2half_rn(oy);
                }
            }
        }
    }
}

__global__ void __launch_bounds__(256) proj_qkv_kernel(
    const float* __restrict__ bq, const float* __restrict__ bk,
    const float* __restrict__ bv) {
    extern __shared__ __half smh[];
    const int z = blockIdx.z;
    const int row0 = blockIdx.y * 128, col0 = blockIdx.x * 128;
    if (z == 0) {
        proj_body<1>(g_q16, g_Wq16, bq, g_Qh, smh, row0, col0);
    } else if (z == 1) {
        proj_body<1>(g_k16, g_Wk16, bk, g_Kh, smh, row0, col0);
    } else {
        proj_body<2>(g_v16, g_Wv16, bv, g_Vt, smh, row0, col0);
    }
}

__global__ void __launch_bounds__(256) proj_o_kernel(const float* __restrict__ bo,
                                                     float* __restrict__ out) {
    extern __shared__ __half smh[];
    proj_body<0>(g_att, g_Wo16, bo, out, smh, blockIdx.y * 128, blockIdx.x * 128);
}

// ---------------------------------------------------------------------------
// Flash attention (causal), fp16 mma + ldmatrix, PAIR-processed K/V tiles:
// 4 K-buffers + 4 V-buffers, ONE cp_wait + ONE __syncthreads per 2 tiles.
// 8 warps x 16 rows, reversed-qt schedule.
// ---------------------------------------------------------------------------
constexpr int AT = 72;            // half stride (36 words)
constexpr int KV_TILE = 64 * AT;  // halfs
constexpr int ATTN_SMEM_HALFS = 4 * KV_TILE + 4 * KV_TILE + 128 * AT;  // 46080
constexpr int ATTN_SMEM_BYTES = ATTN_SMEM_HALFS * 2;  // 92160

__global__ void __launch_bounds__(256, 2) attn_kernel(float* /*unused*/) {
    extern __shared__ __half smh[];

    const int tid = threadIdx.x;
    const int wid = tid >> 5;
    const int lid = tid & 31;
    const int g = lid >> 2;
    const int t4 = lid & 3;
    const int qq = lid >> 3;
    const int rr = lid & 7;
    const int qt = (int)gridDim.x - 1 - (int)blockIdx.x;  // long CTAs first
    const int bh = blockIdx.y;
    const int rb = wid * 16;

    const __half* Qg = g_Qh + ((size_t)bh * Sc + qt * 128) * DKc;
    const __half* Kg = g_Kh + (size_t)bh * Sc * DKc;
    const __half* Vg = g_Vt + (size_t)bh * DKc * Sc;

    const uint32_t smb = smem_u32(smh);
    const uint32_t ksb = smb;                       // 4 x [64][AT]
    const uint32_t vtb = smb + 4 * KV_TILE * 2;     // 4 x [64][AT]
    const uint32_t pab = smb + 8 * KV_TILE * 2;     // [128][AT] Q staging / P
    __half* Pall = smh + 8 * KV_TILE;

    const uint32_t a_off =
        (uint32_t)(((qq & 1) * 8 + rr) * AT + (qq >> 1) * 8) * 2;
    const uint32_t b_off =
        (uint32_t)(((qq >> 1) * 8 + rr) * AT + (qq & 1) * 8) * 2;

    auto load_kv = [&](int kt, int buf) {
#pragma unroll
        for (int i = 0; i < 2; i++) {
            const int ch = tid + i * 256;
            const int r = ch >> 3;
            const int c = ch & 7;
            const uint32_t so = (uint32_t)(buf * KV_TILE + r * AT + c * 8) * 2;
            cp_async16(ksb + so, Kg + ((size_t)(kt * 64 + r)) * DKc + c * 8);
            cp_async16(vtb + so, Vg + (size_t)r * Sc + kt * 64 + c * 8);
        }
        cp_commit();
    };

    // Stage Q
    {
#pragma unroll
        for (int i = 0; i < 4; i++) {
            const int ch = tid + i * 256;
            const int r = ch >> 3;
            const int c = ch & 7;
            cp_async16(pab + (uint32_t)(r * AT + c * 8) * 2,
                       Qg + (size_t)r * DKc + c * 8);
        }
        cp_commit();
    }
    load_kv(0, 0);
    load_kv(1, 1);
    cp_wait<2>();  // Q staged (kv0/kv1 may still be in flight)
    __syncthreads();

    uint32_t qf[4][4];
    {
        const uint32_t qbase = pab + (uint32_t)(rb * AT) * 2;
#pragma unroll
        for (int ks = 0; ks < 4; ks++)
            ldm_x4(qf[ks][0], qf[ks][1], qf[ks][2], qf[ks][3],
                   qbase + a_off + ks * 32);
    }

    __half* Pw = Pall + rb * AT;
    uint32_t* Pwu = reinterpret_cast<uint32_t*>(Pw);
    const uint32_t pwbase = pab + (uint32_t)(rb * AT) * 2;

    float m0 = -1e30f, m1 = -1e30f, l0 = 0.0f, l1 = 0.0f;
    float Oacc[8][4] = {};
    const float scale = 0.125f;

    // Per-tile processing (S, softmax, PV) for tile kt in K/V buffer `buf`.
    auto process = [&](int kt, int buf) {
        const uint32_t kbase = ksb + (uint32_t)(buf * KV_TILE) * 2;
        const uint32_t vbase = vtb + (uint32_t)(buf * KV_TILE) * 2;

        // S = Q @ K^T
        float sacc[8][4] = {};
#pragma unroll
        for (int ks = 0; ks < 4; ks++) {
            uint32_t bf[8][2];
#pragma unroll
            for (int p = 0; p < 4; p++) {
                ldm_x4(bf[2 * p][0], bf[2 * p][1], bf[2 * p + 1][0],
                       bf[2 * p + 1][1],
                       kbase + b_off + (uint32_t)(p * 16 * AT) * 2 + ks * 32);
            }
#pragma unroll
            for (int nt = 0; nt < 8; nt++) mma_f16(sacc[nt], qf[ks], bf[nt]);
        }

        // scale + causal mask
#pragma unroll
        for (int nt = 0; nt < 8; nt++) {
            sacc[nt][0] *= scale;
            sacc[nt][1] *= scale;
            sacc[nt][2] *= scale;
            sacc[nt][3] *= scale;
        }
        if (kt >= 2 * qt) {
            const int cb = kt * 64;
            const int r0g = qt * 128 + rb + g;
            const int r1g = r0g + 8;
#pragma unroll
            for (int nt = 0; nt < 8; nt++) {
                const int c0 = cb + nt * 8 + 2 * t4;
                if (c0 > r0g)     sacc[nt][0] = -1e30f;
                if (c0 + 1 > r0g) sacc[nt][1] = -1e30f;
                if (c0 > r1g)     sacc[nt][2] = -1e30f;
                if (c0 + 1 > r1g) sacc[nt][3] = -1e30f;
            }
        }

        // row max
        float pm0 = -1e30f, pm1 = -1e30f;
#pragma unroll
        for (int nt = 0; nt < 8; nt++) {
            pm0 = fmaxf(pm0, fmaxf(sacc[nt][0], sacc[nt][1]));
            pm1 = fmaxf(pm1, fmaxf(sacc[nt][2], sacc[nt][3]));
        }
        pm0 = fmaxf(pm0, __shfl_xor_sync(0xffffffffu, pm0, 1));
        pm0 = fmaxf(pm0, __shfl_xor_sync(0xffffffffu, pm0, 2));
        pm1 = fmaxf(pm1, __shfl_xor_sync(0xffffffffu, pm1, 1));
        pm1 = fmaxf(pm1, __shfl_xor_sync(0xffffffffu, pm1, 2));

        const float mn0 = fmaxf(m0, pm0);
        const float mn1 = fmaxf(m1, pm1);
        const float a0 = __expf(m0 - mn0);
        const float a1 = __expf(m1 - mn1);
        m0 = mn0;
        m1 = mn1;

        // exp, P write, partial sums
        float ps0 = 0.0f, ps1 = 0.0f;
#pragma unroll
        for (int nt = 0; nt < 8; nt++) {
            const float p0 = __expf(sacc[nt][0] - mn0);
            const float p1 = __expf(sacc[nt][1] - mn0);
            const float p2 = __expf(sacc[nt][2] - mn1);
            const float p3 = __expf(sacc[nt][3] - mn1);
            ps0 += p0 + p1;
            ps1 += p2 + p3;
            Pwu[g * 36 + 4 * nt + t4] = pack_h2(p0, p1);
            Pwu[(g + 8) * 36 + 4 * nt + t4] = pack_h2(p2, p3);
        }
        ps0 += __shfl_xor_sync(0xffffffffu, ps0, 1);
        ps0 += __shfl_xor_sync(0xffffffffu, ps0, 2);
        ps1 += __shfl_xor_sync(0xffffffffu, ps1, 1);
        ps1 += __shfl_xor_sync(0xffffffffu, ps1, 2);
        l0 = l0 * a0 + ps0;
        l1 = l1 * a1 + ps1;

#pragma unroll
        for (int nt = 0; nt < 8; nt++) {
            Oacc[nt][0] *= a0;
            Oacc[nt][1] *= a0;
            Oacc[nt][2] *= a1;
            Oacc[nt][3] *= a1;
        }
        __syncwarp();

        // O += P @ V
#pragma unroll
        for (int ks = 0; ks < 4; ks++) {
            uint32_t af[4];
            ldm_x4(af[0], af[1], af[2], af[3], pwbase + a_off + ks * 32);
            uint32_t bf[8][2];
#pragma unroll
            for (int p = 0; p < 4; p++) {
                ldm_x4(bf[2 * p][0], bf[2 * p][1], bf[2 * p + 1][0],
                       bf[2 * p + 1][1],
                       vbase + b_off + (uint32_t)(p * 16 * AT) * 2 + ks * 32);
            }
#pragma unroll
            for (int nt = 0; nt < 8; nt++) mma_f16(Oacc[nt], af, bf[nt]);
        }
        __syncwarp();  // PV reads done before next P overwrite
    };

    const int npairs = qt + 1;  // tiles = 2*qt + 2 (even)
    for (int p = 0; p < npairs; ++p) {
        cp_wait<0>();      // both tiles of pair p resident
        __syncthreads();   // publish pair p; all warps done with pair p-1 bufs
        if (p + 1 < npairs) {
            const int nb = ((p + 1) & 1) * 2;
            load_kv(2 * p + 2, nb);
            load_kv(2 * p + 3, nb + 1);
        }
        const int pb = (p & 1) * 2;
        process(2 * p, pb);
        process(2 * p + 1, pb + 1);
    }

    // Epilogue
    const int b = bh >> 4;
    const int h = bh & 15;
    const float inv0 = 1.0f / l0;
    const float inv1 = 1.0f / l1;
    const int s0 = qt * 128 + rb + g;
    const int s1 = s0 + 8;
#pragma unroll
    for (int nt = 0; nt < 8; nt++) {
        const int c = nt * 8 + 2 * t4;
        __half2 o0 = __floats2half2_rn(Oacc[nt][0] * inv0, Oacc[nt][1] * inv0);
        __half2 o1 = __floats2half2_rn(Oacc[nt][2] * inv1, Oacc[nt][3] * inv1);
        *reinterpret_cast<__half2*>(g_att + ((size_t)(b * Sc + s0)) * Dc + h * 64 + c) = o0;
        *reinterpret_cast<__half2*>(g_att + ((size_t)(b * Sc + s1)) * Dc + h * 64 + c) = o1;
    }
}

// ---------------------------------------------------------------------------
extern "C" void kernel_launch(void* const* d_in, const int* in_sizes, int n_in,
                              void* d_out, int out_size) {
    const float* q  = (const float*)d_in[0];
    const float* k  = (const float*)d_in[1];
    const float* v  = (const float*)d_in[2];
    // d_in[3] = mask (causal implemented directly)
    const float* Wq = (const float*)d_in[4];
    const float* bq = (const float*)d_in[5];
    const float* Wk = (const float*)d_in[6];
    const float* bk = (const float*)d_in[7];
    const float* Wv = (const float*)d_in[8];
    const float* bv = (const float*)d_in[9];
    const float* Wo = (const float*)d_in[10];
    const float* bo = (const float*)d_in[11];
    float* out = (float*)d_out;

    cudaFuncSetAttribute(proj_qkv_kernel,
                         cudaFuncAttributeMaxDynamicSharedMemorySize, PROJ_SMEM);
    cudaFuncSetAttribute(proj_o_kernel,
                         cudaFuncAttributeMaxDynamicSharedMemorySize, PROJ_SMEM);
    cudaFuncSetAttribute(attn_kernel,
                         cudaFuncAttributeMaxDynamicSharedMemorySize, ATTN_SMEM_BYTES);

    cvt_kernel<<<2048, 256>>>(q, k, v, Wq, Wk, Wv, Wo);

    dim3 qkvgrid(Dc / 128, Mc / 128, 3);  // (8, 32, 3)
    proj_qkv_kernel<<<qkvgrid, 256, PROJ_SMEM>>>(bq, bk, bv);

    dim3 agrid(Sc / 128, Bc * Hc);        // (16, 32)
    attn_kernel<<<agrid, 256, ATTN_SMEM_BYTES>>>(out);

    dim3 ogrid(Dc / 128, Mc / 128);       // (8, 32)
    proj_o_kernel<<<ogrid, 256, PROJ_SMEM>>>(bo, out);
}